// round 3
// baseline (speedup 1.0000x reference)
#include <cuda_runtime.h>
#include <math.h>

// Problem dims
#define NT    512
#define NBATCH 64
#define NIN   512
#define NH    1024
#define NOUT  128
#define KC 32          // K-chunk for the tile GEMM

// ----------------------------------------------------------------------------
// Scratch (__device__ globals: the sanctioned no-alloc scratch mechanism)
// g_P[t][b][j]: j<1024 = new_ha accumulator, j>=1024 = pre-relu u accumulator.
//   precompute STOREs x-part + bias (so each graph replay resets state);
//   step kernels RED-accumulate the h-part on top.
// g_HB[t][b][j]: new_hb accumulator, pre-initialized with b_u2h by precompute.
// ----------------------------------------------------------------------------
__device__ float g_P[(size_t)NT * NBATCH * 2048];          // 256 MB
__device__ float g_HB[(size_t)NT * NBATCH * NH];           // 128 MB
__device__ float g_OUTACC[NBATCH * NOUT];                  // logits accumulator

// ----------------------------------------------------------------------------
// 64x64 output tile GEMM over Klen (multiple of KC).
//   A: [64 rows(b)][Klen] at A[b*lda + k]   (optional relu on load)
//   W: [64 rows(j)][Klen] at W[j*ldw + k]
//   O: out[b*ldo + j];  STORE: O = acc + bias[j]; else RED (atomicAdd)
// 256 threads, 4x4 per-thread tile, register prefetch of next K-chunk.
// ----------------------------------------------------------------------------
template<bool RELU, bool STORE>
__device__ __forceinline__ void gemm64(
    float* __restrict__ smem,
    const float* __restrict__ A, int lda,
    const float* __restrict__ W, int ldw,
    int Klen,
    float* __restrict__ O, int ldo,
    const float* __restrict__ bias)
{
    float (*sA)[68] = (float (*)[68])smem;              // [KC][68]
    float (*sW)[68] = (float (*)[68])(smem + KC * 68);  // [KC][68]

    const int tid = threadIdx.x;
    const int row = tid >> 2;          // 0..63 (staging row)
    const int q   = tid & 3;           // 0..3  (staging quad)
    const int jt  = (tid & 15) << 2;   // 0..60 (compute j base)
    const int bt  = (tid >> 4) << 2;   // 0..60 (compute b base)

    float acc[4][4];
    #pragma unroll
    for (int i = 0; i < 4; ++i)
        #pragma unroll
        for (int j = 0; j < 4; ++j) acc[i][j] = 0.0f;

    const float* pa = A + (size_t)row * lda + q * 4;
    const float* pw = W + (size_t)row * ldw + q * 4;

    float4 a0 = *(const float4*)(pa);
    float4 a1 = *(const float4*)(pa + 16);
    float4 w0 = *(const float4*)(pw);
    float4 w1 = *(const float4*)(pw + 16);

    const int nch = Klen / KC;
    for (int c = 0; c < nch; ++c) {
        if (RELU) {
            a0.x = fmaxf(a0.x, 0.f); a0.y = fmaxf(a0.y, 0.f);
            a0.z = fmaxf(a0.z, 0.f); a0.w = fmaxf(a0.w, 0.f);
            a1.x = fmaxf(a1.x, 0.f); a1.y = fmaxf(a1.y, 0.f);
            a1.z = fmaxf(a1.z, 0.f); a1.w = fmaxf(a1.w, 0.f);
        }
        __syncthreads();
        {
            int kq = q * 4;
            sA[kq + 0][row] = a0.x; sA[kq + 1][row] = a0.y;
            sA[kq + 2][row] = a0.z; sA[kq + 3][row] = a0.w;
            sA[kq + 16][row] = a1.x; sA[kq + 17][row] = a1.y;
            sA[kq + 18][row] = a1.z; sA[kq + 19][row] = a1.w;
            sW[kq + 0][row] = w0.x; sW[kq + 1][row] = w0.y;
            sW[kq + 2][row] = w0.z; sW[kq + 3][row] = w0.w;
            sW[kq + 16][row] = w1.x; sW[kq + 17][row] = w1.y;
            sW[kq + 18][row] = w1.z; sW[kq + 19][row] = w1.w;
        }
        __syncthreads();
        if (c + 1 < nch) {
            const float* na = pa + (c + 1) * KC;
            const float* nw = pw + (c + 1) * KC;
            a0 = *(const float4*)(na);
            a1 = *(const float4*)(na + 16);
            w0 = *(const float4*)(nw);
            w1 = *(const float4*)(nw + 16);
        }
        #pragma unroll
        for (int k = 0; k < KC; ++k) {
            float4 av = *(const float4*)&sA[k][bt];
            float4 wv = *(const float4*)&sW[k][jt];
            float a[4] = {av.x, av.y, av.z, av.w};
            float w[4] = {wv.x, wv.y, wv.z, wv.w};
            #pragma unroll
            for (int bi = 0; bi < 4; ++bi)
                #pragma unroll
                for (int ji = 0; ji < 4; ++ji)
                    acc[bi][ji] = fmaf(a[bi], w[ji], acc[bi][ji]);
        }
    }

    #pragma unroll
    for (int bi = 0; bi < 4; ++bi) {
        #pragma unroll
        for (int ji = 0; ji < 4; ++ji) {
            float* dst = O + (size_t)(bt + bi) * ldo + (jt + ji);
            if (STORE) *dst = acc[bi][ji] + bias[jt + ji];
            else       atomicAdd(dst, acc[bi][ji]);   // RED.ADD.F32
        }
    }
}

// ----------------------------------------------------------------------------
// Precompute (fully parallel): P[t][b][0:1024]    = b_i2h + x[t] @ Wx_i2h^T
//                              P[t][b][1024:2048] = b_i2u + x[t] @ Wx_i2u^T
// Also stores b_u2h into every g_HB[t] and b_u2o into g_OUTACC (pure stores
// -> replays are idempotent). grid: (32 n-tiles, 512 t), 256 threads.
// ----------------------------------------------------------------------------
__global__ void __launch_bounds__(256)
precompute_kernel(const float* __restrict__ x,
                  const float* __restrict__ W_i2h, const float* __restrict__ b_i2h,
                  const float* __restrict__ W_i2u, const float* __restrict__ b_i2u,
                  const float* __restrict__ b_u2h, const float* __restrict__ b_u2o)
{
    __shared__ float smem[2 * KC * 68];

    const int nt = blockIdx.x;       // 0..31
    const int t  = blockIdx.y;       // 0..511
    const int j0 = nt * 64;

    const float* A = x + (size_t)t * NBATCH * NIN;     // [64][512]
    const float* W;
    const float* bias;
    if (j0 < NH) { W = W_i2h + (size_t)j0 * (NIN + NH);        bias = b_i2h + j0; }
    else         { W = W_i2u + (size_t)(j0 - NH) * (NIN + NH); bias = b_i2u + (j0 - NH); }
    float* O = g_P + (size_t)t * (NBATCH * 2048) + j0;

    gemm64<false, true>(smem, A, NIN, W, NIN + NH, NIN, O, 2048, bias);

    if (nt < 16) {   // g_HB[t][b][j0..j0+63] = b_u2h
        float* hb = g_HB + (size_t)t * (NBATCH * NH);
        for (int idx = threadIdx.x; idx < 64 * 64; idx += 256) {
            int b = idx >> 6, jj = idx & 63;
            hb[(size_t)b * NH + j0 + jj] = b_u2h[j0 + jj];
        }
    }
    if (t == 0 && nt == 31) {
        for (int idx = threadIdx.x; idx < NBATCH * NOUT; idx += 256)
            g_OUTACC[idx] = b_u2o[idx & (NOUT - 1)];
    }
}

// ----------------------------------------------------------------------------
// Fused step kernel K(t), t in [0, NT]. 128 blocks, single wave.
//   blocks [0,64):   ph1(t)   (active if t < NT)  — h-part of i2h|i2u,
//                    RED into g_P[t]. Reads ha(t-1) (g_P[t-1] or h0[0]).
//   blocks [64,128): ph2(t-1) (active if t >= 1)  — u2h,
//                    RED into g_HB[t-1]. Reads u(t-1) (relu of g_P[t-1]
//                    upper half) and hb(t-2) (g_HB[t-2] or h0[1]).
// Read/write sets of the two halves are disjoint; K(t) depends only on K(t-1).
// ----------------------------------------------------------------------------
__global__ void __launch_bounds__(256)
step_kernel(int t,
            const float* __restrict__ h0,
            const float* __restrict__ W_i2h, const float* __restrict__ W_i2u,
            const float* __restrict__ W_u2h)
{
    __shared__ float smem[2 * KC * 68];
    const int bid = blockIdx.x;

    if (bid < 64) {
        if (t >= NT) return;
        // ph1: 2048 outputs (new_ha | pre-relu u), K = 1024 over ha(t-1)
        const int j0 = (bid >> 1) * 64;        // 0..1984
        const int k0 = (bid & 1) * 512;        // 0 or 512
        const float* A;
        int lda;
        if (t == 0) { A = h0 + k0;                                      lda = NH;   }
        else        { A = g_P + (size_t)(t - 1) * (NBATCH * 2048) + k0; lda = 2048; }
        const float* W = (j0 < NH)
            ? (W_i2h + (size_t)j0 * (NIN + NH) + NIN + k0)
            : (W_i2u + (size_t)(j0 - NH) * (NIN + NH) + NIN + k0);
        float* O = g_P + (size_t)t * (NBATCH * 2048) + j0;
        gemm64<false, false>(smem, A, lda, W, NIN + NH, 512, O, 2048, nullptr);
    } else {
        if (t < 1) return;
        const int s  = t - 1;                  // the step ph2 computes
        const int b2 = bid - 64;
        const int j0 = (b2 >> 2) * 64;         // 0..960
        const int k0 = (b2 & 3) * 512;         // 0,512,1024,1536
        const float* W = W_u2h + (size_t)j0 * (2 * NH) + k0;
        float* O = g_HB + (size_t)s * (NBATCH * NH) + j0;
        if (k0 < NH) {   // u half (relu on load)
            const float* A = g_P + (size_t)s * (NBATCH * 2048) + NH + k0;
            gemm64<true, false>(smem, A, 2048, W, 2 * NH, 512, O, NH, nullptr);
        } else {         // hb half
            const int kh = k0 - NH;
            const float* A;
            int lda;
            if (s == 0) { A = h0 + (size_t)NBATCH * NH + kh;               lda = NH; }
            else        { A = g_HB + (size_t)(s - 1) * (NBATCH * NH) + kh; lda = NH; }
            gemm64<false, false>(smem, A, lda, W, 2 * NH, 512, O, NH, nullptr);
        }
    }
}

// ----------------------------------------------------------------------------
// Logits: g_OUTACC += [relu(u(511)) | hb(510)] @ W_u2o^T   (32 blocks)
// ----------------------------------------------------------------------------
__global__ void __launch_bounds__(256)
logits_kernel(const float* __restrict__ W_u2o)
{
    __shared__ float smem[2 * KC * 68];
    const int o0 = (blockIdx.x >> 4) * 64;     // 0 or 64
    const int k0 = (blockIdx.x & 15) * 128;    // 0..1920
    const int tl = NT - 1;
    const float* W = W_u2o + (size_t)o0 * (2 * NH) + k0;
    float* O = g_OUTACC + o0;
    if (k0 < NH) {
        const float* A = g_P + (size_t)tl * (NBATCH * 2048) + NH + k0;
        gemm64<true, false>(smem, A, 2048, W, 2 * NH, 128, O, NOUT, nullptr);
    } else {
        const float* A = g_HB + (size_t)(tl - 1) * (NBATCH * NH) + (k0 - NH);
        gemm64<false, false>(smem, A, NH, W, 2 * NH, 128, O, NOUT, nullptr);
    }
}

// ----------------------------------------------------------------------------
// log_softmax over g_OUTACC rows -> d_out. 1 block, 8 warps.
// ----------------------------------------------------------------------------
__global__ void __launch_bounds__(256)
softmax_kernel(float* __restrict__ d_out)
{
    const int lane = threadIdx.x & 31;
    const int wid  = threadIdx.x >> 5;
    for (int b = wid; b < NBATCH; b += 8) {
        const float* rowp = g_OUTACC + (size_t)b * NOUT;
        float m = -INFINITY;
        for (int o = lane; o < NOUT; o += 32) m = fmaxf(m, rowp[o]);
        #pragma unroll
        for (int off = 16; off; off >>= 1) m = fmaxf(m, __shfl_xor_sync(0xFFFFFFFFu, m, off));
        float s = 0.0f;
        for (int o = lane; o < NOUT; o += 32) s += expf(rowp[o] - m);
        #pragma unroll
        for (int off = 16; off; off >>= 1) s += __shfl_xor_sync(0xFFFFFFFFu, s, off);
        float lse = logf(s) + m;
        for (int o = lane; o < NOUT; o += 32)
            d_out[(size_t)b * NOUT + o] = rowp[o] - lse;
    }
}

// ----------------------------------------------------------------------------
// Launch. Inputs (metadata order): x, h0, W_i2h, b_i2h, W_i2u, b_i2u,
//                                  W_u2h, b_u2h, W_u2o, b_u2o
// Pure kernel launches on the capture stream; no syncs, no allocs, no
// inter-block waits anywhere -> graph-capturable and deadlock-free.
// ----------------------------------------------------------------------------
extern "C" void kernel_launch(void* const* d_in, const int* in_sizes, int n_in,
                              void* d_out, int out_size)
{
    const float* x     = (const float*)d_in[0];
    const float* h0    = (const float*)d_in[1];
    const float* W_i2h = (const float*)d_in[2];
    const float* b_i2h = (const float*)d_in[3];
    const float* W_i2u = (const float*)d_in[4];
    const float* b_i2u = (const float*)d_in[5];
    const float* W_u2h = (const float*)d_in[6];
    const float* b_u2h = (const float*)d_in[7];
    const float* W_u2o = (const float*)d_in[8];
    const float* b_u2o = (const float*)d_in[9];
    float* out = (float*)d_out;

    dim3 gpre(32, NT);
    precompute_kernel<<<gpre, 256>>>(x, W_i2h, b_i2h, W_i2u, b_i2u, b_u2h, b_u2o);
    for (int t = 0; t <= NT; ++t)
        step_kernel<<<128, 256>>>(t, h0, W_i2h, W_i2u, W_u2h);
    logits_kernel<<<32, 256>>>(W_u2o);
    softmax_kernel<<<1, 256>>>(out);
}

// round 4
// speedup vs baseline: 1.7646x; 1.7646x over previous
#include <cuda_runtime.h>
#include <cuda_bf16.h>
#include <math.h>
#include <stdint.h>

// Problem dims
#define NT    512
#define NBATCH 64
#define NIN   512
#define NH    1024
#define NOUT  128
#define KC 32          // fp32 gemm64 K-chunk (precompute / logits)

// MMA step-kernel tiling
#define SROW 40        // smem row stride in bf16 (80B; conflict-free ldmatrix)

// ----------------------------------------------------------------------------
// Scratch (__device__ globals)
// g_P[t][b][j]: j<1024 ha accumulator, j>=1024 pre-relu u accumulator.
//   precompute STOREs x-part + bias; step kernels RED-accumulate h-part.
// g_HB[t][b][j]: hb accumulator (pre-init b_u2h).
// g_Wh*: [2048 j][1024 k] bf16 hi/lo of the h-columns of [W_i2h; W_i2u].
// g_Wu*: [1024 j][2048 k] bf16 hi/lo of W_u2h.
// ----------------------------------------------------------------------------
__device__ float g_P [(size_t)NT * NBATCH * 2048];         // 256 MB
__device__ float g_HB[(size_t)NT * NBATCH * NH];           // 128 MB
__device__ float g_OUTACC[NBATCH * NOUT];
__device__ __nv_bfloat16 g_Wh_hi[2048 * 1024];
__device__ __nv_bfloat16 g_Wh_lo[2048 * 1024];
__device__ __nv_bfloat16 g_Wu_hi[1024 * 2048];
__device__ __nv_bfloat16 g_Wu_lo[1024 * 2048];

// ============================================================================
// fp32 SIMT 64x64 tile GEMM (precompute + logits) — unchanged, proven.
// ============================================================================
template<bool RELU, bool STORE>
__device__ __forceinline__ void gemm64(
    float* __restrict__ smem,
    const float* __restrict__ A, int lda,
    const float* __restrict__ W, int ldw,
    int Klen,
    float* __restrict__ O, int ldo,
    const float* __restrict__ bias)
{
    float (*sA)[68] = (float (*)[68])smem;
    float (*sW)[68] = (float (*)[68])(smem + KC * 68);

    const int tid = threadIdx.x;
    const int row = tid >> 2;
    const int q   = tid & 3;
    const int jt  = (tid & 15) << 2;
    const int bt  = (tid >> 4) << 2;

    float acc[4][4];
    #pragma unroll
    for (int i = 0; i < 4; ++i)
        #pragma unroll
        for (int j = 0; j < 4; ++j) acc[i][j] = 0.0f;

    const float* pa = A + (size_t)row * lda + q * 4;
    const float* pw = W + (size_t)row * ldw + q * 4;

    float4 a0 = *(const float4*)(pa);
    float4 a1 = *(const float4*)(pa + 16);
    float4 w0 = *(const float4*)(pw);
    float4 w1 = *(const float4*)(pw + 16);

    const int nch = Klen / KC;
    for (int c = 0; c < nch; ++c) {
        if (RELU) {
            a0.x = fmaxf(a0.x, 0.f); a0.y = fmaxf(a0.y, 0.f);
            a0.z = fmaxf(a0.z, 0.f); a0.w = fmaxf(a0.w, 0.f);
            a1.x = fmaxf(a1.x, 0.f); a1.y = fmaxf(a1.y, 0.f);
            a1.z = fmaxf(a1.z, 0.f); a1.w = fmaxf(a1.w, 0.f);
        }
        __syncthreads();
        {
            int kq = q * 4;
            sA[kq + 0][row] = a0.x; sA[kq + 1][row] = a0.y;
            sA[kq + 2][row] = a0.z; sA[kq + 3][row] = a0.w;
            sA[kq + 16][row] = a1.x; sA[kq + 17][row] = a1.y;
            sA[kq + 18][row] = a1.z; sA[kq + 19][row] = a1.w;
            sW[kq + 0][row] = w0.x; sW[kq + 1][row] = w0.y;
            sW[kq + 2][row] = w0.z; sW[kq + 3][row] = w0.w;
            sW[kq + 16][row] = w1.x; sW[kq + 17][row] = w1.y;
            sW[kq + 18][row] = w1.z; sW[kq + 19][row] = w1.w;
        }
        __syncthreads();
        if (c + 1 < nch) {
            const float* na = pa + (c + 1) * KC;
            const float* nw = pw + (c + 1) * KC;
            a0 = *(const float4*)(na);
            a1 = *(const float4*)(na + 16);
            w0 = *(const float4*)(nw);
            w1 = *(const float4*)(nw + 16);
        }
        #pragma unroll
        for (int k = 0; k < KC; ++k) {
            float4 av = *(const float4*)&sA[k][bt];
            float4 wv = *(const float4*)&sW[k][jt];
            float a[4] = {av.x, av.y, av.z, av.w};
            float w[4] = {wv.x, wv.y, wv.z, wv.w};
            #pragma unroll
            for (int bi = 0; bi < 4; ++bi)
                #pragma unroll
                for (int ji = 0; ji < 4; ++ji)
                    acc[bi][ji] = fmaf(a[bi], w[ji], acc[bi][ji]);
        }
    }

    #pragma unroll
    for (int bi = 0; bi < 4; ++bi) {
        #pragma unroll
        for (int ji = 0; ji < 4; ++ji) {
            float* dst = O + (size_t)(bt + bi) * ldo + (jt + ji);
            if (STORE) *dst = acc[bi][ji] + bias[jt + ji];
            else       atomicAdd(dst, acc[bi][ji]);
        }
    }
}

// ============================================================================
// MMA helpers
// ============================================================================
__device__ __forceinline__ uint32_t s2u(const void* p) {
    return (uint32_t)__cvta_generic_to_shared(p);
}
__device__ __forceinline__ void ldsm4(uint32_t* r, uint32_t addr) {
    asm volatile("ldmatrix.sync.aligned.m8n8.x4.shared.b16 {%0,%1,%2,%3}, [%4];"
        : "=r"(r[0]), "=r"(r[1]), "=r"(r[2]), "=r"(r[3]) : "r"(addr));
}
__device__ __forceinline__ void mma_bf16(float* d, const uint32_t* a,
                                         uint32_t b0, uint32_t b1) {
    asm volatile(
        "mma.sync.aligned.m16n8k16.row.col.f32.bf16.bf16.f32 "
        "{%0,%1,%2,%3},{%4,%5,%6,%7},{%8,%9},{%0,%1,%2,%3};"
        : "+f"(d[0]), "+f"(d[1]), "+f"(d[2]), "+f"(d[3])
        : "r"(a[0]), "r"(a[1]), "r"(a[2]), "r"(a[3]), "r"(b0), "r"(b1));
}

// ----------------------------------------------------------------------------
// Split-bf16 MMA tile: O[64 b][128 j] += A[64][256] @ W[256][... per j]^T
// A fp32 (consumer-side hi/lo split, optional relu); W pre-split bf16 hi/lo,
// row-major [j][k]. 256 threads = 8 warps (2 m x 4 n), warp tile m32 x n32.
// K = 256, chunks of 32. RED (atomicAdd) into O.
// ----------------------------------------------------------------------------
__device__ __forceinline__ void mma_tile(
    const float* __restrict__ A, int lda, bool relu,
    const __nv_bfloat16* __restrict__ Whi,
    const __nv_bfloat16* __restrict__ Wlo, int ldw,
    float* __restrict__ O, int ldo,
    __nv_bfloat16* __restrict__ sm)
{
    __nv_bfloat16* sAhi = sm;                    // [64][SROW]
    __nv_bfloat16* sAlo = sm + 64 * SROW;
    __nv_bfloat16* sBhi = sm + 2 * 64 * SROW;    // [128][SROW]
    __nv_bfloat16* sBlo = sBhi + 128 * SROW;

    const int tid  = threadIdx.x;
    const int lane = tid & 31;
    const int wid  = tid >> 5;
    const int m0   = (wid & 1) * 32;
    const int n0   = (wid >> 1) * 32;

    // staging maps
    int ar[2], ac[2], br[2], bq[2];
    const float* pA[2];
    const __nv_bfloat16 *pBh[2], *pBl[2];
    #pragma unroll
    for (int i = 0; i < 2; ++i) {
        int p = tid + i * 256;
        ar[i] = p >> 3;          // 0..63
        ac[i] = (p & 7) * 4;     // fp32 col
        pA[i] = A + (size_t)ar[i] * lda + ac[i];
        br[i] = p >> 2;          // 0..127
        bq[i] = (p & 3) * 8;     // bf16 col
        pBh[i] = Whi + (size_t)br[i] * ldw + bq[i];
        pBl[i] = Wlo + (size_t)br[i] * ldw + bq[i];
    }

    // ldmatrix per-lane base addresses
    const uint32_t aOff = (uint32_t)((lane & 15) * (SROW * 2) + ((lane >> 4) << 4));
    const uint32_t bOff = (uint32_t)(((lane & 7) + ((lane >> 4) << 3)) * (SROW * 2)
                                     + (((lane >> 3) & 1) << 4));
    const uint32_t uAhi = s2u(sAhi) + aOff;
    const uint32_t uAlo = s2u(sAlo) + aOff;
    const uint32_t uBhi = s2u(sBhi) + bOff;
    const uint32_t uBlo = s2u(sBlo) + bOff;

    float acc[2][4][4];
    #pragma unroll
    for (int mi = 0; mi < 2; ++mi)
        #pragma unroll
        for (int ni = 0; ni < 4; ++ni)
            #pragma unroll
            for (int r = 0; r < 4; ++r) acc[mi][ni][r] = 0.0f;

    // prefetch chunk 0
    float4 av[2]; uint4 bvh[2], bvl[2];
    #pragma unroll
    for (int i = 0; i < 2; ++i) {
        av[i]  = *(const float4*)(pA[i]);
        bvh[i] = *(const uint4*)(pBh[i]);
        bvl[i] = *(const uint4*)(pBl[i]);
    }

    const int NCH = 256 / 32;
    for (int c = 0; c < NCH; ++c) {
        __syncthreads();
        // ---- store staged chunk (A: fp32 -> hi/lo split) ----
        #pragma unroll
        for (int i = 0; i < 2; ++i) {
            float4 v = av[i];
            if (relu) {
                v.x = fmaxf(v.x, 0.f); v.y = fmaxf(v.y, 0.f);
                v.z = fmaxf(v.z, 0.f); v.w = fmaxf(v.w, 0.f);
            }
            __nv_bfloat16 hx = __float2bfloat16_rn(v.x);
            __nv_bfloat16 hy = __float2bfloat16_rn(v.y);
            __nv_bfloat16 hz = __float2bfloat16_rn(v.z);
            __nv_bfloat16 hw = __float2bfloat16_rn(v.w);
            __nv_bfloat162* dh = (__nv_bfloat162*)&sAhi[ar[i] * SROW + ac[i]];
            dh[0] = __halves2bfloat162(hx, hy);
            dh[1] = __halves2bfloat162(hz, hw);
            __nv_bfloat162* dl = (__nv_bfloat162*)&sAlo[ar[i] * SROW + ac[i]];
            dl[0] = __halves2bfloat162(
                __float2bfloat16_rn(v.x - __bfloat162float(hx)),
                __float2bfloat16_rn(v.y - __bfloat162float(hy)));
            dl[1] = __halves2bfloat162(
                __float2bfloat16_rn(v.z - __bfloat162float(hz)),
                __float2bfloat16_rn(v.w - __bfloat162float(hw)));
            *(uint4*)&sBhi[br[i] * SROW + bq[i]] = bvh[i];
            *(uint4*)&sBlo[br[i] * SROW + bq[i]] = bvl[i];
        }
        __syncthreads();
        if (c + 1 < NCH) {   // prefetch next chunk
            #pragma unroll
            for (int i = 0; i < 2; ++i) {
                av[i]  = *(const float4*)(pA[i]  + (c + 1) * 32);
                bvh[i] = *(const uint4*)(pBh[i] + (c + 1) * 32);
                bvl[i] = *(const uint4*)(pBl[i] + (c + 1) * 32);
            }
        }
        // ---- compute: 2 k16 steps ----
        #pragma unroll
        for (int kk = 0; kk < 2; ++kk) {
            const uint32_t kb = kk * 32;   // bytes
            uint32_t ah[2][4], al[2][4], bh[2][4], bl[2][4];
            ldsm4(ah[0], uAhi + (m0 +  0) * (SROW * 2) + kb);
            ldsm4(ah[1], uAhi + (m0 + 16) * (SROW * 2) + kb);
            ldsm4(al[0], uAlo + (m0 +  0) * (SROW * 2) + kb);
            ldsm4(al[1], uAlo + (m0 + 16) * (SROW * 2) + kb);
            ldsm4(bh[0], uBhi + (n0 +  0) * (SROW * 2) + kb);
            ldsm4(bh[1], uBhi + (n0 + 16) * (SROW * 2) + kb);
            ldsm4(bl[0], uBlo + (n0 +  0) * (SROW * 2) + kb);
            ldsm4(bl[1], uBlo + (n0 + 16) * (SROW * 2) + kb);
            #pragma unroll
            for (int mi = 0; mi < 2; ++mi)
                #pragma unroll
                for (int ni = 0; ni < 4; ++ni) {
                    const int np = ni >> 1, hf = (ni & 1) << 1;
                    mma_bf16(acc[mi][ni], ah[mi], bh[np][hf], bh[np][hf + 1]);
                    mma_bf16(acc[mi][ni], ah[mi], bl[np][hf], bl[np][hf + 1]);
                    mma_bf16(acc[mi][ni], al[mi], bh[np][hf], bh[np][hf + 1]);
                }
        }
    }

    // ---- epilogue: RED into O ----
    const int g  = lane >> 2;
    const int tg = lane & 3;
    #pragma unroll
    for (int mi = 0; mi < 2; ++mi)
        #pragma unroll
        for (int ni = 0; ni < 4; ++ni) {
            const int brow = m0 + mi * 16 + g;
            const int jc   = n0 + ni * 8 + tg * 2;
            float* d0 = O + (size_t)brow * ldo + jc;
            atomicAdd(d0,     acc[mi][ni][0]);
            atomicAdd(d0 + 1, acc[mi][ni][1]);
            float* d1 = O + (size_t)(brow + 8) * ldo + jc;
            atomicAdd(d1,     acc[mi][ni][2]);
            atomicAdd(d1 + 1, acc[mi][ni][3]);
        }
}

// ============================================================================
// Weight split: fp32 -> bf16 hi/lo (once per replay; pure stores)
// ============================================================================
__global__ void __launch_bounds__(256)
wsplit_kernel(const float* __restrict__ W_i2h, const float* __restrict__ W_i2u,
              const float* __restrict__ W_u2h)
{
    const size_t g0 = ((size_t)blockIdx.x * 256 + threadIdx.x) * 4;
    #pragma unroll
    for (int e = 0; e < 4; ++e) {
        size_t i = g0 + e;
        float v;
        __nv_bfloat16 *dh, *dl;
        if (i < (size_t)2048 * 1024) {
            int j = (int)(i >> 10), k = (int)(i & 1023);
            v = (j < NH) ? W_i2h[(size_t)j * (NIN + NH) + NIN + k]
                         : W_i2u[(size_t)(j - NH) * (NIN + NH) + NIN + k];
            dh = &g_Wh_hi[i]; dl = &g_Wh_lo[i];
        } else {
            size_t i2 = i - (size_t)2048 * 1024;   // [1024][2048]
            v = W_u2h[i2];
            dh = &g_Wu_hi[i2]; dl = &g_Wu_lo[i2];
        }
        __nv_bfloat16 h = __float2bfloat16_rn(v);
        *dh = h;
        *dl = __float2bfloat16_rn(v - __bfloat162float(h));
    }
}

// ============================================================================
// Precompute (fp32 SIMT): x-part + bias into g_P; b_u2h into g_HB; b_u2o init.
// ============================================================================
__global__ void __launch_bounds__(256)
precompute_kernel(const float* __restrict__ x,
                  const float* __restrict__ W_i2h, const float* __restrict__ b_i2h,
                  const float* __restrict__ W_i2u, const float* __restrict__ b_i2u,
                  const float* __restrict__ b_u2h, const float* __restrict__ b_u2o)
{
    __shared__ float smem[2 * KC * 68];

    const int nt = blockIdx.x;       // 0..31
    const int t  = blockIdx.y;       // 0..511
    const int j0 = nt * 64;

    const float* A = x + (size_t)t * NBATCH * NIN;
    const float* W;
    const float* bias;
    if (j0 < NH) { W = W_i2h + (size_t)j0 * (NIN + NH);        bias = b_i2h + j0; }
    else         { W = W_i2u + (size_t)(j0 - NH) * (NIN + NH); bias = b_i2u + (j0 - NH); }
    float* O = g_P + (size_t)t * (NBATCH * 2048) + j0;

    gemm64<false, true>(smem, A, NIN, W, NIN + NH, NIN, O, 2048, bias);

    if (nt < 16) {
        float* hb = g_HB + (size_t)t * (NBATCH * NH);
        for (int idx = threadIdx.x; idx < 64 * 64; idx += 256) {
            int b = idx >> 6, jj = idx & 63;
            hb[(size_t)b * NH + j0 + jj] = b_u2h[j0 + jj];
        }
    }
    if (t == 0 && nt == 31) {
        for (int idx = threadIdx.x; idx < NBATCH * NOUT; idx += 256)
            g_OUTACC[idx] = b_u2o[idx & (NOUT - 1)];
    }
}

// ============================================================================
// Fused step kernel K(t): 128 blocks.
//  blocks [0,64):  ph1(t)  (t<NT): 16 j-tiles(128) x 4 k-splits(256) over ha(t-1)
//  blocks [64,128): ph2(t-1) (t>=1): 8 j-tiles(128) x 8 k-splits(256) over
//                   [relu(u(t-1)) | hb(t-2)]
// ============================================================================
__global__ void __launch_bounds__(256)
step_kernel(int t, const float* __restrict__ h0)
{
    __shared__ __align__(16) __nv_bfloat16 sm[2 * 64 * SROW + 2 * 128 * SROW];
    const int bid = blockIdx.x;

    if (bid < 64) {
        if (t >= NT) return;
        const int j0 = (bid >> 2) * 128;
        const int k0 = (bid & 3) * 256;
        const float* A;
        int lda;
        if (t == 0) { A = h0 + k0;                                      lda = NH;   }
        else        { A = g_P + (size_t)(t - 1) * (NBATCH * 2048) + k0; lda = 2048; }
        mma_tile(A, lda, false,
                 g_Wh_hi + (size_t)j0 * 1024 + k0,
                 g_Wh_lo + (size_t)j0 * 1024 + k0, 1024,
                 g_P + (size_t)t * (NBATCH * 2048) + j0, 2048, sm);
    } else {
        if (t < 1) return;
        const int s  = t - 1;
        const int b2 = bid - 64;
        const int j0 = (b2 >> 3) * 128;
        const int k0 = (b2 & 7) * 256;
        float* O = g_HB + (size_t)s * (NBATCH * NH) + j0;
        const __nv_bfloat16* Whi = g_Wu_hi + (size_t)j0 * 2048 + k0;
        const __nv_bfloat16* Wlo = g_Wu_lo + (size_t)j0 * 2048 + k0;
        if (k0 < NH) {   // u half (relu on staging)
            const float* A = g_P + (size_t)s * (NBATCH * 2048) + NH + k0;
            mma_tile(A, 2048, true, Whi, Wlo, 2048, O, NH, sm);
        } else {         // hb half
            const int kh = k0 - NH;
            const float* A;
            int lda;
            if (s == 0) { A = h0 + (size_t)NBATCH * NH + kh;               lda = NH; }
            else        { A = g_HB + (size_t)(s - 1) * (NBATCH * NH) + kh; lda = NH; }
            mma_tile(A, lda, false, Whi, Wlo, 2048, O, NH, sm);
        }
    }
}

// ============================================================================
// Logits (fp32 SIMT, once): g_OUTACC += [relu(u(511)) | hb(510)] @ W_u2o^T
// ============================================================================
__global__ void __launch_bounds__(256)
logits_kernel(const float* __restrict__ W_u2o)
{
    __shared__ float smem[2 * KC * 68];
    const int o0 = (blockIdx.x >> 4) * 64;
    const int k0 = (blockIdx.x & 15) * 128;
    const int tl = NT - 1;
    const float* W = W_u2o + (size_t)o0 * (2 * NH) + k0;
    float* O = g_OUTACC + o0;
    if (k0 < NH) {
        const float* A = g_P + (size_t)tl * (NBATCH * 2048) + NH + k0;
        gemm64<true, false>(smem, A, 2048, W, 2 * NH, 128, O, NOUT, nullptr);
    } else {
        const float* A = g_HB + (size_t)(tl - 1) * (NBATCH * NH) + (k0 - NH);
        gemm64<false, false>(smem, A, NH, W, 2 * NH, 128, O, NOUT, nullptr);
    }
}

__global__ void __launch_bounds__(256)
softmax_kernel(float* __restrict__ d_out)
{
    const int lane = threadIdx.x & 31;
    const int wid  = threadIdx.x >> 5;
    for (int b = wid; b < NBATCH; b += 8) {
        const float* rowp = g_OUTACC + (size_t)b * NOUT;
        float m = -INFINITY;
        for (int o = lane; o < NOUT; o += 32) m = fmaxf(m, rowp[o]);
        #pragma unroll
        for (int off = 16; off; off >>= 1) m = fmaxf(m, __shfl_xor_sync(0xFFFFFFFFu, m, off));
        float s = 0.0f;
        for (int o = lane; o < NOUT; o += 32) s += expf(rowp[o] - m);
        #pragma unroll
        for (int off = 16; off; off >>= 1) s += __shfl_xor_sync(0xFFFFFFFFu, s, off);
        float lse = logf(s) + m;
        for (int o = lane; o < NOUT; o += 32)
            d_out[(size_t)b * NOUT + o] = rowp[o] - lse;
    }
}

// ============================================================================
// Launch. Inputs: x, h0, W_i2h, b_i2h, W_i2u, b_i2u, W_u2h, b_u2h, W_u2o, b_u2o
// ============================================================================
extern "C" void kernel_launch(void* const* d_in, const int* in_sizes, int n_in,
                              void* d_out, int out_size)
{
    const float* x     = (const float*)d_in[0];
    const float* h0    = (const float*)d_in[1];
    const float* W_i2h = (const float*)d_in[2];
    const float* b_i2h = (const float*)d_in[3];
    const float* W_i2u = (const float*)d_in[4];
    const float* b_i2u = (const float*)d_in[5];
    const float* W_u2h = (const float*)d_in[6];
    const float* b_u2h = (const float*)d_in[7];
    const float* W_u2o = (const float*)d_in[8];
    const float* b_u2o = (const float*)d_in[9];
    float* out = (float*)d_out;

    wsplit_kernel<<<4096, 256>>>(W_i2h, W_i2u, W_u2h);
    dim3 gpre(32, NT);
    precompute_kernel<<<gpre, 256>>>(x, W_i2h, b_i2h, W_i2u, b_i2u, b_u2h, b_u2o);
    for (int t = 0; t < NT; ++t)
        step_kernel<<<128, 256>>>(t, h0);
    logits_kernel<<<32, 256>>>(W_u2o);
    softmax_kernel<<<1, 256>>>(out);
}

// round 6
// speedup vs baseline: 3.5599x; 2.0174x over previous
#include <cuda_runtime.h>
#include <cuda_bf16.h>
#include <math.h>
#include <stdint.h>

// Problem dims
#define NT    512
#define NBATCH 64
#define NIN   512
#define NH    1024
#define NOUT  128
#define KC 32          // fp32 gemm64 K-chunk (logits only)

// MMA tiling: block tile 64(b) x 128(j), K-chunk 64, 8 warps (2m x 4n), warp m32 x n32
#define KCH  64
#define SROW 72        // smem row stride in bf16 (144B; 16B-aligned rows, conflict-free)

// ----------------------------------------------------------------------------
// Scratch (__device__ globals)
// g_P[t][b][j]: j<1024 ha accumulator, j>=1024 pre-relu u accumulator.
//   precompute STOREs x-part + bias (replay-idempotent); steps RED h-part.
// g_HB[t][b][j]: hb accumulator (pre-init b_u2h by precompute).
// g_Wh: [2048 j][1536 k] bf16 of [W_i2h; W_i2u] (x-cols 0..511, h-cols 512..1535)
// g_Wu: [1024 j][2048 k] bf16 of W_u2h.
// ----------------------------------------------------------------------------
__device__ float g_P [(size_t)NT * NBATCH * 2048];         // 256 MB
__device__ float g_HB[(size_t)NT * NBATCH * NH];           // 128 MB
__device__ float g_OUTACC[NBATCH * NOUT];
__device__ __nv_bfloat16 g_Wh[(size_t)2048 * 1536];
__device__ __nv_bfloat16 g_Wu[(size_t)1024 * 2048];

// ============================================================================
// MMA helpers
// ============================================================================
__device__ __forceinline__ uint32_t s2u(const void* p) {
    return (uint32_t)__cvta_generic_to_shared(p);
}
__device__ __forceinline__ void ldsm4(uint32_t* r, uint32_t addr) {
    asm volatile("ldmatrix.sync.aligned.m8n8.x4.shared.b16 {%0,%1,%2,%3}, [%4];"
        : "=r"(r[0]), "=r"(r[1]), "=r"(r[2]), "=r"(r[3]) : "r"(addr));
}
__device__ __forceinline__ void mma_bf16(float* d, const uint32_t* a,
                                         uint32_t b0, uint32_t b1) {
    asm volatile(
        "mma.sync.aligned.m16n8k16.row.col.f32.bf16.bf16.f32 "
        "{%0,%1,%2,%3},{%4,%5,%6,%7},{%8,%9},{%0,%1,%2,%3};"
        : "+f"(d[0]), "+f"(d[1]), "+f"(d[2]), "+f"(d[3])
        : "r"(a[0]), "r"(a[1]), "r"(a[2]), "r"(a[3]), "r"(b0), "r"(b1));
}

// ----------------------------------------------------------------------------
// bf16 MMA tile: O[64 b][128 j] (+)= A[64][Klen] @ W[Klen per j row]^T
//   A fp32 in gmem (converted to bf16 during smem staging, optional relu);
//   W bf16 row-major [j][k].
//   STORE: O = acc + bias[j] (one writer per output); else RED (atomicAdd).
// 256 threads. Klen multiple of KCH.
// ----------------------------------------------------------------------------
template<bool STORE>
__device__ __forceinline__ void mma_tile(
    const float* __restrict__ A, int lda, bool relu,
    const __nv_bfloat16* __restrict__ W, int ldw, int Klen,
    float* __restrict__ O, int ldo,
    const float* __restrict__ bias,
    __nv_bfloat16* __restrict__ sm)
{
    __nv_bfloat16* sA = sm;               // [64][SROW]
    __nv_bfloat16* sB = sm + 64 * SROW;   // [128][SROW]

    const int tid  = threadIdx.x;
    const int lane = tid & 31;
    const int wid  = tid >> 5;
    const int m0   = (wid & 1) * 32;
    const int n0   = (wid >> 1) * 32;

    // staging maps: A 64x64 fp32 -> 4 float4/thread; B 128x64 bf16 -> 4 uint4/thread
    int ar[4], ac[4], br[4], bq[4];
    const float* pA[4];
    const __nv_bfloat16* pB[4];
    #pragma unroll
    for (int i = 0; i < 4; ++i) {
        int p = tid + i * 256;
        ar[i] = p >> 4;            // 0..63
        ac[i] = (p & 15) << 2;     // fp32 col 0..60
        pA[i] = A + (size_t)ar[i] * lda + ac[i];
        br[i] = p >> 3;            // 0..127
        bq[i] = (p & 7) << 3;      // bf16 col 0..56
        pB[i] = W + (size_t)br[i] * ldw + bq[i];
    }

    // ldmatrix per-lane base addresses
    const uint32_t aOff = (uint32_t)((lane & 15) * (SROW * 2) + ((lane >> 4) << 4));
    const uint32_t bOff = (uint32_t)(((lane & 7) + ((lane >> 4) << 3)) * (SROW * 2)
                                     + (((lane >> 3) & 1) << 4));
    const uint32_t uA = s2u(sA) + aOff;
    const uint32_t uB = s2u(sB) + bOff;

    float acc[2][4][4];
    #pragma unroll
    for (int mi = 0; mi < 2; ++mi)
        #pragma unroll
        for (int ni = 0; ni < 4; ++ni)
            #pragma unroll
            for (int r = 0; r < 4; ++r) acc[mi][ni][r] = 0.0f;

    // prefetch chunk 0
    float4 aR[4]; uint4 bR[4];
    #pragma unroll
    for (int i = 0; i < 4; ++i) {
        aR[i] = *(const float4*)(pA[i]);
        bR[i] = *(const uint4*)(pB[i]);
    }

    const int nch = Klen / KCH;
    for (int c = 0; c < nch; ++c) {
        __syncthreads();   // previous chunk's compute done; smem reusable
        #pragma unroll
        for (int i = 0; i < 4; ++i) {
            float4 v = aR[i];
            if (relu) {
                v.x = fmaxf(v.x, 0.f); v.y = fmaxf(v.y, 0.f);
                v.z = fmaxf(v.z, 0.f); v.w = fmaxf(v.w, 0.f);
            }
            __nv_bfloat162* da = (__nv_bfloat162*)&sA[ar[i] * SROW + ac[i]];
            da[0] = __halves2bfloat162(__float2bfloat16_rn(v.x), __float2bfloat16_rn(v.y));
            da[1] = __halves2bfloat162(__float2bfloat16_rn(v.z), __float2bfloat16_rn(v.w));
            *(uint4*)&sB[br[i] * SROW + bq[i]] = bR[i];
        }
        __syncthreads();
        if (c + 1 < nch) {   // prefetch next chunk (latency overlaps compute)
            #pragma unroll
            for (int i = 0; i < 4; ++i) {
                aR[i] = *(const float4*)(pA[i] + (c + 1) * KCH);
                bR[i] = *(const uint4*)(pB[i] + (c + 1) * KCH);
            }
        }
        #pragma unroll
        for (int kk = 0; kk < 4; ++kk) {
            const uint32_t kb = kk * 32;   // bytes (16 bf16)
            uint32_t ah[2][4], bh[2][4];
            ldsm4(ah[0], uA + (m0 +  0) * (SROW * 2) + kb);
            ldsm4(ah[1], uA + (m0 + 16) * (SROW * 2) + kb);
            ldsm4(bh[0], uB + (n0 +  0) * (SROW * 2) + kb);
            ldsm4(bh[1], uB + (n0 + 16) * (SROW * 2) + kb);
            #pragma unroll
            for (int mi = 0; mi < 2; ++mi)
                #pragma unroll
                for (int ni = 0; ni < 4; ++ni) {
                    const int np = ni >> 1, hf = (ni & 1) << 1;
                    mma_bf16(acc[mi][ni], ah[mi], bh[np][hf], bh[np][hf + 1]);
                }
        }
    }

    // ---- epilogue ----
    const int g  = lane >> 2;
    const int tg = lane & 3;
    #pragma unroll
    for (int mi = 0; mi < 2; ++mi)
        #pragma unroll
        for (int ni = 0; ni < 4; ++ni) {
            const int brow = m0 + mi * 16 + g;
            const int jc   = n0 + ni * 8 + tg * 2;
            float* d0 = O + (size_t)brow * ldo + jc;
            float* d1 = O + (size_t)(brow + 8) * ldo + jc;
            if (STORE) {
                float b0 = bias[jc], b1 = bias[jc + 1];
                *(float2*)d0 = make_float2(acc[mi][ni][0] + b0, acc[mi][ni][1] + b1);
                *(float2*)d1 = make_float2(acc[mi][ni][2] + b0, acc[mi][ni][3] + b1);
            } else {
                atomicAdd(d0,     acc[mi][ni][0]);
                atomicAdd(d0 + 1, acc[mi][ni][1]);
                atomicAdd(d1,     acc[mi][ni][2]);
                atomicAdd(d1 + 1, acc[mi][ni][3]);
            }
        }
}

// ============================================================================
// Weight convert: fp32 -> bf16 (once per replay; pure stores).
// grid.x in [0, 5120): blocks [0,3072) cover g_Wh rows (2048 j x 1536 k),
// blocks [3072,5120) cover g_Wu (1024 j x 2048 k). 32-bit indexing only.
// ============================================================================
__global__ void __launch_bounds__(256)
wconv_kernel(const float* __restrict__ W_i2h, const float* __restrict__ W_i2u,
             const float* __restrict__ W_u2h)
{
    const int b = blockIdx.x;
    if (b < 3072) {
        // g_Wh: each block does 1024 contiguous elems of one (j, k-quarter)
        // 3072 blocks = 2048 rows * 1.5 (1536 = 1.5 * 1024)
        unsigned base = (unsigned)b * 1024u;            // element index in g_Wh
        unsigned j = base / 1536u;
        unsigned k = base - j * 1536u;
        const float* src = (j < NH) ? (W_i2h + (size_t)j * 1536 + k)
                                    : (W_i2u + (size_t)(j - NH) * 1536 + k);
        __nv_bfloat16* dst = g_Wh + base;
        // rows are 1536 long; a 1024-chunk can straddle at most one row boundary
        unsigned t4 = threadIdx.x * 4u;
        unsigned rem = 1536u - k;                        // elems left in this row
        #pragma unroll
        for (int e = 0; e < 4; ++e) {
            unsigned idx = t4 + e;
            float v;
            if (idx < rem) v = src[idx];
            else {
                unsigned j2 = j + 1 + (idx - rem) / 1536u;
                unsigned k2 = (idx - rem) % 1536u;
                v = (j2 < NH) ? W_i2h[(size_t)j2 * 1536 + k2]
                              : W_i2u[(size_t)(j2 - NH) * 1536 + k2];
            }
            dst[idx] = __float2bfloat16_rn(v);
        }
    } else {
        unsigned base = (unsigned)(b - 3072) * 1024u;    // element index in g_Wu
        unsigned t4 = threadIdx.x * 4u;
        #pragma unroll
        for (int e = 0; e < 4; ++e)
            g_Wu[base + t4 + e] = __float2bfloat16_rn(W_u2h[base + t4 + e]);
    }
}

// ============================================================================
// Precompute (bf16 MMA): g_P[t][b][j] = bias[j] + x[t] @ Wx[j]^T  (STORE)
// Also b_u2h into g_HB[t], b_u2o into g_OUTACC. grid (16 j-tiles, 512 t).
// ============================================================================
__global__ void __launch_bounds__(256)
precompute_kernel(const float* __restrict__ x,
                  const float* __restrict__ b_i2h, const float* __restrict__ b_i2u,
                  const float* __restrict__ b_u2h, const float* __restrict__ b_u2o)
{
    __shared__ __align__(16) __nv_bfloat16 sm[64 * SROW + 128 * SROW];
    const int jt = blockIdx.x;       // 0..15
    const int t  = blockIdx.y;       // 0..511
    const int j0 = jt * 128;

    const float* bias = (j0 < NH) ? (b_i2h + j0) : (b_i2u + (j0 - NH));
    mma_tile<true>(x + (size_t)t * NBATCH * NIN, NIN, false,
                   g_Wh + (size_t)j0 * 1536, 1536, NIN,
                   g_P + (size_t)t * (NBATCH * 2048) + j0, 2048, bias, sm);

    if (jt < 8) {   // g_HB[t][b][j0..j0+127] = b_u2h
        float* hb = g_HB + (size_t)t * (NBATCH * NH);
        for (int idx = threadIdx.x; idx < 64 * 128; idx += 256) {
            int b = idx >> 7, jj = idx & 127;
            hb[(size_t)b * NH + j0 + jj] = b_u2h[j0 + jj];
        }
    }
    if (t == 0 && jt == 15) {
        for (int idx = threadIdx.x; idx < NBATCH * NOUT; idx += 256)
            g_OUTACC[idx] = b_u2o[idx & (NOUT - 1)];
    }
}

// ============================================================================
// Fused step kernel K(t): 128 blocks.
//  blocks [0,64):  ph1(t):   16 j-tiles(128) x 4 k-splits(256) over ha(t-1),
//                  RED into g_P[t].  (W cols 512.. of g_Wh)
//  blocks [64,128): ph2(t-1) (t>=1): 8 j-tiles(128) x 8 k-splits(256) over
//                  [relu(u(t-1)) | hb(t-2)], RED into g_HB[t-1].
// ============================================================================
__global__ void __launch_bounds__(256)
step_kernel(int t, const float* __restrict__ h0)
{
    __shared__ __align__(16) __nv_bfloat16 sm[64 * SROW + 128 * SROW];
    const int bid = blockIdx.x;

    if (bid < 64) {
        const int j0 = (bid >> 2) * 128;
        const int k0 = (bid & 3) * 256;
        const float* A;
        int lda;
        if (t == 0) { A = h0 + k0;                                      lda = NH;   }
        else        { A = g_P + (size_t)(t - 1) * (NBATCH * 2048) + k0; lda = 2048; }
        mma_tile<false>(A, lda, false,
                        g_Wh + (size_t)j0 * 1536 + NIN + k0, 1536, 256,
                        g_P + (size_t)t * (NBATCH * 2048) + j0, 2048, nullptr, sm);
    } else {
        if (t < 1) return;
        const int s  = t - 1;
        const int b2 = bid - 64;
        const int j0 = (b2 >> 3) * 128;
        const int k0 = (b2 & 7) * 256;
        float* O = g_HB + (size_t)s * (NBATCH * NH) + j0;
        const __nv_bfloat16* W = g_Wu + (size_t)j0 * 2048 + k0;
        if (k0 < NH) {   // u half (relu on staging)
            const float* A = g_P + (size_t)s * (NBATCH * 2048) + NH + k0;
            mma_tile<false>(A, 2048, true, W, 2048, 256, O, NH, nullptr, sm);
        } else {         // hb half
            const int kh = k0 - NH;
            const float* A;
            int lda;
            if (s == 0) { A = h0 + (size_t)NBATCH * NH + kh;               lda = NH; }
            else        { A = g_HB + (size_t)(s - 1) * (NBATCH * NH) + kh; lda = NH; }
            mma_tile<false>(A, lda, false, W, 2048, 256, O, NH, nullptr, sm);
        }
    }
}

// ============================================================================
// fp32 SIMT 64x64 GEMM for the one-off logits (full precision where it's free)
// ============================================================================
template<bool RELU>
__device__ __forceinline__ void gemm64(
    float* __restrict__ smem,
    const float* __restrict__ A, int lda,
    const float* __restrict__ W, int ldw,
    int Klen, float* __restrict__ O, int ldo)
{
    float (*sA)[68] = (float (*)[68])smem;
    float (*sW)[68] = (float (*)[68])(smem + KC * 68);
    const int tid = threadIdx.x;
    const int row = tid >> 2;
    const int q   = tid & 3;
    const int jt  = (tid & 15) << 2;
    const int bt  = (tid >> 4) << 2;

    float acc[4][4];
    #pragma unroll
    for (int i = 0; i < 4; ++i)
        #pragma unroll
        for (int j = 0; j < 4; ++j) acc[i][j] = 0.0f;

    const float* pa = A + (size_t)row * lda + q * 4;
    const float* pw = W + (size_t)row * ldw + q * 4;
    float4 a0 = *(const float4*)(pa);
    float4 a1 = *(const float4*)(pa + 16);
    float4 w0 = *(const float4*)(pw);
    float4 w1 = *(const float4*)(pw + 16);

    const int nch = Klen / KC;
    for (int c = 0; c < nch; ++c) {
        if (RELU) {
            a0.x = fmaxf(a0.x, 0.f); a0.y = fmaxf(a0.y, 0.f);
            a0.z = fmaxf(a0.z, 0.f); a0.w = fmaxf(a0.w, 0.f);
            a1.x = fmaxf(a1.x, 0.f); a1.y = fmaxf(a1.y, 0.f);
            a1.z = fmaxf(a1.z, 0.f); a1.w = fmaxf(a1.w, 0.f);
        }
        __syncthreads();
        {
            int kq = q * 4;
            sA[kq + 0][row] = a0.x; sA[kq + 1][row] = a0.y;
            sA[kq + 2][row] = a0.z; sA[kq + 3][row] = a0.w;
            sA[kq + 16][row] = a1.x; sA[kq + 17][row] = a1.y;
            sA[kq + 18][row] = a1.z; sA[kq + 19][row] = a1.w;
            sW[kq + 0][row] = w0.x; sW[kq + 1][row] = w0.y;
            sW[kq + 2][row] = w0.z; sW[kq + 3][row] = w0.w;
            sW[kq + 16][row] = w1.x; sW[kq + 17][row] = w1.y;
            sW[kq + 18][row] = w1.z; sW[kq + 19][row] = w1.w;
        }
        __syncthreads();
        if (c + 1 < nch) {
            const float* na = pa + (c + 1) * KC;
            const float* nw = pw + (c + 1) * KC;
            a0 = *(const float4*)(na);
            a1 = *(const float4*)(na + 16);
            w0 = *(const float4*)(nw);
            w1 = *(const float4*)(nw + 16);
        }
        #pragma unroll
        for (int k = 0; k < KC; ++k) {
            float4 av = *(const float4*)&sA[k][bt];
            float4 wv = *(const float4*)&sW[k][jt];
            float a[4] = {av.x, av.y, av.z, av.w};
            float w[4] = {wv.x, wv.y, wv.z, wv.w};
            #pragma unroll
            for (int bi = 0; bi < 4; ++bi)
                #pragma unroll
                for (int ji = 0; ji < 4; ++ji)
                    acc[bi][ji] = fmaf(a[bi], w[ji], acc[bi][ji]);
        }
    }
    #pragma unroll
    for (int bi = 0; bi < 4; ++bi)
        #pragma unroll
        for (int ji = 0; ji < 4; ++ji)
            atomicAdd(O + (size_t)(bt + bi) * ldo + (jt + ji), acc[bi][ji]);
}

__global__ void __launch_bounds__(256)
logits_kernel(const float* __restrict__ W_u2o)
{
    __shared__ float smem[2 * KC * 68];
    const int o0 = (blockIdx.x >> 4) * 64;
    const int k0 = (blockIdx.x & 15) * 128;
    const int tl = NT - 1;
    const float* W = W_u2o + (size_t)o0 * (2 * NH) + k0;
    float* O = g_OUTACC + o0;
    if (k0 < NH) {
        const float* A = g_P + (size_t)tl * (NBATCH * 2048) + NH + k0;
        gemm64<true>(smem, A, 2048, W, 2 * NH, 128, O, NOUT);
    } else {
        const float* A = g_HB + (size_t)(tl - 1) * (NBATCH * NH) + (k0 - NH);
        gemm64<false>(smem, A, NH, W, 2 * NH, 128, O, NOUT);
    }
}

__global__ void __launch_bounds__(256)
softmax_kernel(float* __restrict__ d_out)
{
    const int lane = threadIdx.x & 31;
    const int wid  = threadIdx.x >> 5;
    for (int b = wid; b < NBATCH; b += 8) {
        const float* rowp = g_OUTACC + (size_t)b * NOUT;
        float m = -INFINITY;
        for (int o = lane; o < NOUT; o += 32) m = fmaxf(m, rowp[o]);
        #pragma unroll
        for (int off = 16; off; off >>= 1) m = fmaxf(m, __shfl_xor_sync(0xFFFFFFFFu, m, off));
        float s = 0.0f;
        for (int o = lane; o < NOUT; o += 32) s += expf(rowp[o] - m);
        #pragma unroll
        for (int off = 16; off; off >>= 1) s += __shfl_xor_sync(0xFFFFFFFFu, s, off);
        float lse = logf(s) + m;
        for (int o = lane; o < NOUT; o += 32)
            d_out[(size_t)b * NOUT + o] = rowp[o] - lse;
    }
}

// ============================================================================
// Launch. Inputs: x, h0, W_i2h, b_i2h, W_i2u, b_i2u, W_u2h, b_u2h, W_u2o, b_u2o
// ============================================================================
extern "C" void kernel_launch(void* const* d_in, const int* in_sizes, int n_in,
                              void* d_out, int out_size)
{
    const float* x     = (const float*)d_in[0];
    const float* h0    = (const float*)d_in[1];
    const float* W_i2h = (const float*)d_in[2];
    const float* b_i2h = (const float*)d_in[3];
    const float* W_i2u = (const float*)d_in[4];
    const float* b_i2u = (const float*)d_in[5];
    const float* W_u2h = (const float*)d_in[6];
    const float* b_u2h = (const float*)d_in[7];
    const float* W_u2o = (const float*)d_in[8];
    const float* b_u2o = (const float*)d_in[9];
    float* out = (float*)d_out;

    wconv_kernel<<<5120, 256>>>(W_i2h, W_i2u, W_u2h);
    dim3 gpre(16, NT);
    precompute_kernel<<<gpre, 256>>>(x, b_i2h, b_i2u, b_u2h, b_u2o);
    for (int t = 0; t < NT; ++t)
        step_kernel<<<128, 256>>>(t, h0);
    logits_kernel<<<32, 256>>>(W_u2o);
    softmax_kernel<<<1, 256>>>(out);
}